// round 17
// baseline (speedup 1.0000x reference)
#include <cuda_runtime.h>
#include <cuda_bf16.h>
#include <cuda_pipeline.h>
#include <mma.h>
#include <math.h>

using namespace nvcuda;

// Problem constants
#define B_  2
#define S_  2048
#define D_  1024
#define H_  16
#define DK_ 64
#define M_  (B_*S_)

// GEMM tiling (at the HMMA.16816 throughput ceiling: ~103us/GEMM, 2 CTAs/SM)
#define BM 128
#define BN 128
#define BK 32
#define LDT 40
#define TILE_ELEMS (BM*LDT)
#define STAGE_ELEMS (4*TILE_ELEMS)
#define SMEM_BYTES (2*STAGE_ELEMS*2)

// Flash v10 smem (bytes): 128 queries/CTA, warp-owns-rows, single KV buffer.
// Q hi/lo 36864 + KV 36864 + P 36864 = 110592 -> 2 CTAs/SM.
#define FQH 0
#define FQL 18432
#define FKV 36864            // Kh 9216, Kl 9216, Vh 9216, Vl 9216 -> ends 73728
#define FP  73728            // 128 rows x 288B (hi cols 0..63, lo at +72 elems)
#define FLASH_SMEM 110592

// Scratch (device globals — no allocation allowed)
__device__ __nv_bfloat16 g_X1h[M_*D_];
__device__ __nv_bfloat16 g_X1l[M_*D_];
__device__ __nv_bfloat16 g_X2h[M_*D_];
__device__ __nv_bfloat16 g_X2l[M_*D_];
__device__ __nv_bfloat16 g_X3h[M_*D_];
__device__ __nv_bfloat16 g_X3l[M_*D_];
__device__ __nv_bfloat16 g_W1h[D_*D_];
__device__ __nv_bfloat16 g_W1l[D_*D_];
__device__ __nv_bfloat16 g_W2h[D_*D_];
__device__ __nv_bfloat16 g_W2l[D_*D_];
__device__ __nv_bfloat16 g_W3h[D_*D_];
__device__ __nv_bfloat16 g_W3l[D_*D_];
__device__ __nv_bfloat16 g_W4h[D_*D_];
__device__ __nv_bfloat16 g_W4l[D_*D_];
__device__ __nv_bfloat16 g_Qh[M_*D_];
__device__ __nv_bfloat16 g_Ql[M_*D_];
__device__ __nv_bfloat16 g_Kh[M_*D_];
__device__ __nv_bfloat16 g_Kl[M_*D_];
__device__ __nv_bfloat16 g_Vh[M_*D_];
__device__ __nv_bfloat16 g_Vl[M_*D_];

struct GemmSet {
    const __nv_bfloat16* Xh;
    const __nv_bfloat16* Xl;
    const __nv_bfloat16* Wh;
    const __nv_bfloat16* Wl;
    const float* bias;
    float* Y;
    __nv_bfloat16* Yh;
    __nv_bfloat16* Yl;
    int split;
};

// ---------------------------------------------------------------------------
// fp32 -> (hi, lo) bf16 split helpers.
// ---------------------------------------------------------------------------
__device__ __forceinline__ void split4(const float4* src, __nv_bfloat16* hi,
                                       __nv_bfloat16* lo, int i)
{
    float4 v = src[i];
    __nv_bfloat16 h0 = __float2bfloat16(v.x);
    __nv_bfloat16 h1 = __float2bfloat16(v.y);
    __nv_bfloat16 h2 = __float2bfloat16(v.z);
    __nv_bfloat16 h3 = __float2bfloat16(v.w);
    __nv_bfloat162 hh0, hh1, ll0, ll1;
    hh0.x = h0; hh0.y = h1; hh1.x = h2; hh1.y = h3;
    ll0.x = __float2bfloat16(v.x - __bfloat162float(h0));
    ll0.y = __float2bfloat16(v.y - __bfloat162float(h1));
    ll1.x = __float2bfloat16(v.z - __bfloat162float(h2));
    ll1.y = __float2bfloat16(v.w - __bfloat162float(h3));
    *(__nv_bfloat162*)&hi[i*4]     = hh0;
    *(__nv_bfloat162*)&hi[i*4 + 2] = hh1;
    *(__nv_bfloat162*)&lo[i*4]     = ll0;
    *(__nv_bfloat162*)&lo[i*4 + 2] = ll1;
}

// Single launch: converts q,k,v inputs + all four weight matrices.
__global__ __launch_bounds__(256)
void cvt8_kernel(const float4* x1, __nv_bfloat16* x1h, __nv_bfloat16* x1l,
                 const float4* x2, __nv_bfloat16* x2h, __nv_bfloat16* x2l,
                 const float4* x3, __nv_bfloat16* x3h, __nv_bfloat16* x3l,
                 int nx4,
                 const float4* w1, __nv_bfloat16* w1h, __nv_bfloat16* w1l,
                 const float4* w2, __nv_bfloat16* w2h, __nv_bfloat16* w2l,
                 const float4* w3, __nv_bfloat16* w3h, __nv_bfloat16* w3l,
                 const float4* w4, __nv_bfloat16* w4h, __nv_bfloat16* w4l,
                 int nw4)
{
    int i = blockIdx.x * blockDim.x + threadIdx.x;
    if (i < nx4) {
        split4(x1, x1h, x1l, i);
    } else if (i < 2 * nx4) {
        split4(x2, x2h, x2l, i - nx4);
    } else if (i < 3 * nx4) {
        split4(x3, x3h, x3l, i - 2 * nx4);
    } else {
        int j = i - 3 * nx4;
        if (j < nw4) {
            split4(w1, w1h, w1l, j);
        } else if (j < 2 * nw4) {
            split4(w2, w2h, w2l, j - nw4);
        } else if (j < 3 * nw4) {
            split4(w3, w3h, w3l, j - 2 * nw4);
        } else if (j < 4 * nw4) {
            split4(w4, w4h, w4l, j - 3 * nw4);
        }
    }
}

// ---------------------------------------------------------------------------
// Fused GEMM: grid.y selects one of up to 3 (X,W,bias,Y) sets (blockIdx.y>>5).
// ---------------------------------------------------------------------------
__global__ __launch_bounds__(256)
void gemm_wmma_kernel(GemmSet s0, GemmSet s1, GemmSet s2, int N, int K)
{
    extern __shared__ __nv_bfloat16 sm[];
    __shared__ __align__(16) float biasTile[16][136];

    const int tid = threadIdx.x;
    const int wid = tid >> 5;
    const int sel = blockIdx.y >> 5;
    const GemmSet& s = (sel == 0) ? s0 : ((sel == 1) ? s1 : s2);
    const __nv_bfloat16* Xh = s.Xh;
    const __nv_bfloat16* Xl = s.Xl;
    const __nv_bfloat16* Wh = s.Wh;
    const __nv_bfloat16* Wl = s.Wl;

    const int m0  = (blockIdx.y & 31) * BM;
    const int n0  = blockIdx.x * BN;
    const int wm  = (wid & 1) * 64;
    const int wn  = (wid >> 1) * 32;

    for (int idx = tid; idx < 16 * 128; idx += 256) {
        int r = idx >> 7;
        int c = idx & 127;
        biasTile[r][c] = s.bias[n0 + c];
    }
    __syncthreads();

    wmma::fragment<wmma::accumulator, 16, 16, 16, float> acc[4][2];
    for (int mi = 0; mi < 4; mi++)
        for (int ni = 0; ni < 2; ni++)
            wmma::load_matrix_sync(acc[mi][ni], &biasTile[0][wn + ni * 16], 136,
                                   wmma::mem_row_major);

    const int NT = K / BK;

    {
        for (int p = 0; p < 2; p++) {
            int chunk = tid + p * 256;
            int row = chunk >> 2;
            int cc  = chunk & 3;
            const __nv_bfloat16* sa = Xh + (size_t)(m0 + row) * K + cc * 8;
            const __nv_bfloat16* sb = Xl + (size_t)(m0 + row) * K + cc * 8;
            const __nv_bfloat16* sc = Wh + (size_t)(n0 + row) * K + cc * 8;
            const __nv_bfloat16* sd = Wl + (size_t)(n0 + row) * K + cc * 8;
            int so = row * LDT + cc * 8;
            __pipeline_memcpy_async(&sm[so], sa, 16);
            __pipeline_memcpy_async(&sm[TILE_ELEMS + so], sb, 16);
            __pipeline_memcpy_async(&sm[2 * TILE_ELEMS + so], sc, 16);
            __pipeline_memcpy_async(&sm[3 * TILE_ELEMS + so], sd, 16);
        }
        __pipeline_commit();
    }

    for (int t = 0; t < NT; t++) {
        int st = (t & 1) * STAGE_ELEMS;
        if (t + 1 < NT) {
            int k0 = (t + 1) * BK;
            int sn = ((t + 1) & 1) * STAGE_ELEMS;
            for (int p = 0; p < 2; p++) {
                int chunk = tid + p * 256;
                int row = chunk >> 2;
                int cc  = chunk & 3;
                const __nv_bfloat16* sa = Xh + (size_t)(m0 + row) * K + k0 + cc * 8;
                const __nv_bfloat16* sb = Xl + (size_t)(m0 + row) * K + k0 + cc * 8;
                const __nv_bfloat16* sc = Wh + (size_t)(n0 + row) * K + k0 + cc * 8;
                const __nv_bfloat16* sd = Wl + (size_t)(n0 + row) * K + k0 + cc * 8;
                int so = row * LDT + cc * 8;
                __pipeline_memcpy_async(&sm[sn + so], sa, 16);
                __pipeline_memcpy_async(&sm[sn + TILE_ELEMS + so], sb, 16);
                __pipeline_memcpy_async(&sm[sn + 2 * TILE_ELEMS + so], sc, 16);
                __pipeline_memcpy_async(&sm[sn + 3 * TILE_ELEMS + so], sd, 16);
            }
            __pipeline_commit();
            __pipeline_wait_prior(1);
        } else {
            __pipeline_wait_prior(0);
        }
        __syncthreads();

        for (int ks = 0; ks < 2; ks++) {
            int kc = ks * 16;
            wmma::fragment<wmma::matrix_a, 16, 16, 16, __nv_bfloat16, wmma::row_major> ah[4], al[4];
            wmma::fragment<wmma::matrix_b, 16, 16, 16, __nv_bfloat16, wmma::col_major> bh[2], bl[2];
            for (int mi = 0; mi < 4; mi++) {
                int r = wm + mi * 16;
                wmma::load_matrix_sync(ah[mi], &sm[st + r * LDT + kc], LDT);
                wmma::load_matrix_sync(al[mi], &sm[st + TILE_ELEMS + r * LDT + kc], LDT);
            }
            for (int ni = 0; ni < 2; ni++) {
                int r = wn + ni * 16;
                wmma::load_matrix_sync(bh[ni], &sm[st + 2 * TILE_ELEMS + r * LDT + kc], LDT);
                wmma::load_matrix_sync(bl[ni], &sm[st + 3 * TILE_ELEMS + r * LDT + kc], LDT);
            }
            for (int mi = 0; mi < 4; mi++) {
                for (int ni = 0; ni < 2; ni++) {
                    wmma::mma_sync(acc[mi][ni], ah[mi], bh[ni], acc[mi][ni]);
                    wmma::mma_sync(acc[mi][ni], ah[mi], bl[ni], acc[mi][ni]);
                    wmma::mma_sync(acc[mi][ni], al[mi], bh[ni], acc[mi][ni]);
                }
            }
        }
        __syncthreads();
    }

    if (s.split == 0) {
        for (int mi = 0; mi < 4; mi++) {
            for (int ni = 0; ni < 2; ni++) {
                int row = m0 + wm + mi * 16;
                int col = n0 + wn + ni * 16;
                wmma::store_matrix_sync(&s.Y[(size_t)row * N + col], acc[mi][ni], N,
                                        wmma::mem_row_major);
            }
        }
    } else {
        float* stage = (float*)sm;
        for (int mi = 0; mi < 4; mi++)
            for (int ni = 0; ni < 2; ni++)
                wmma::store_matrix_sync(stage + (wm + mi * 16) * 132 + wn + ni * 16,
                                        acc[mi][ni], 132, wmma::mem_row_major);
        __syncthreads();
        for (int idx = tid; idx < 128 * 128; idx += 256) {
            int r = idx >> 7;
            int c = idx & 127;
            float v = stage[r * 132 + c];
            __nv_bfloat16 hv = __float2bfloat16(v);
            size_t g = (size_t)(m0 + r) * N + n0 + c;
            s.Yh[g] = hv;
            s.Yl[g] = __float2bfloat16(v - __bfloat162float(hv));
        }
    }
}

// ---------------------------------------------------------------------------
// Flash v10: warp-owns-rows. CTA = 128 queries, 8 warps, each warp owns 16
// q-rows across all 64 keys. Softmax fully warp-local (m/l in registers),
// P in warp-private smem strips, 2 CTA syncs per tile.
// f32 acc element map (validated R11/R16): rows {0,1,4,5}->lane/4,
// {2,3,6,7}->lane/4+8; cols (lane&3)*2 + (e&1) + 8*(e>>2 &1).
// ---------------------------------------------------------------------------
__device__ __forceinline__ void flash_load_64(char* dst, const __nv_bfloat16* src,
                                              int rowbase, int h, int tid)
{
    for (int p = 0; p < 2; p++) {
        int idx = tid + p * 256;
        int r = idx >> 3;
        int c = idx & 7;
        const __nv_bfloat16* s = src + (size_t)(rowbase + r) * D_ + h * DK_ + c * 8;
        __pipeline_memcpy_async(dst + r * 144 + c * 16, s, 16);
    }
}

__device__ __forceinline__ void flash_load_q(char* dst, const __nv_bfloat16* src,
                                             int rowbase, int h, int tid)
{
    for (int p = 0; p < 4; p++) {
        int idx = tid + p * 256;      // 0..1023
        int r = idx >> 3;             // 0..127
        int c = idx & 7;
        const __nv_bfloat16* s = src + (size_t)(rowbase + r) * D_ + h * DK_ + c * 8;
        __pipeline_memcpy_async(dst + r * 144 + c * 16, s, 16);
    }
}

__device__ __forceinline__ void scale_frag_rows(
    wmma::fragment<wmma::accumulator, 16, 16, 16, float>& f, float s0, float s1)
{
    f.x[0] *= s0; f.x[1] *= s0; f.x[4] *= s0; f.x[5] *= s0;
    f.x[2] *= s1; f.x[3] *= s1; f.x[6] *= s1; f.x[7] *= s1;
}

__device__ __forceinline__ void store_p2(__nv_bfloat16* Prow, int off, float a, float b)
{
    __nv_bfloat16 ha = __float2bfloat16(a);
    __nv_bfloat16 hb = __float2bfloat16(b);
    __nv_bfloat162 hh, ll;
    hh.x = ha; hh.y = hb;
    ll.x = __float2bfloat16(a - __bfloat162float(ha));
    ll.y = __float2bfloat16(b - __bfloat162float(hb));
    *(__nv_bfloat162*)&Prow[off] = hh;
    *(__nv_bfloat162*)&Prow[off + 72] = ll;
}

__global__ __launch_bounds__(256)
void flash_wmma_kernel(const __nv_bfloat16* __restrict__ Qh_g,
                       const __nv_bfloat16* __restrict__ Ql_g,
                       const __nv_bfloat16* __restrict__ Kh_g,
                       const __nv_bfloat16* __restrict__ Kl_g,
                       const __nv_bfloat16* __restrict__ Vh_g,
                       const __nv_bfloat16* __restrict__ Vl_g,
                       __nv_bfloat16* __restrict__ Oh_g,
                       __nv_bfloat16* __restrict__ Ol_g)
{
    extern __shared__ char smb[];

    const int tid  = threadIdx.x;
    const int wid  = tid >> 5;
    const int lane = tid & 31;
    const int qt   = gridDim.x - 1 - blockIdx.x;   // LPT
    const int bhv  = blockIdx.y;
    const int b    = bhv / H_;
    const int h    = bhv % H_;
    const int q0   = qt * 128;

    __nv_bfloat16* Pbuf = (__nv_bfloat16*)(smb + FP);
    float* Obuf = (float*)(smb + FP);   // epilogue alias (same 288B row stride)

    flash_load_q(smb + FQH, Qh_g, b * S_ + q0, h, tid);
    flash_load_q(smb + FQL, Ql_g, b * S_ + q0, h, tid);
    {
        char* kv = smb + FKV;
        flash_load_64(kv,         Kh_g, b * S_, h, tid);
        flash_load_64(kv + 9216,  Kl_g, b * S_, h, tid);
        flash_load_64(kv + 18432, Vh_g, b * S_, h, tid);
        flash_load_64(kv + 27648, Vl_g, b * S_, h, tid);
    }
    __pipeline_commit();

    const int qr   = wid * 16;             // warp's 16 q-rows
    const int rowA = qr + (lane >> 2);
    const int rowB = rowA + 8;
    const int c2   = (lane & 3) * 2;

    float mA = -INFINITY, lA = 0.f;
    float mB = -INFINITY, lB = 0.f;

    wmma::fragment<wmma::accumulator, 16, 16, 16, float> o[4];
    for (int ni = 0; ni < 4; ni++) wmma::fill_fragment(o[ni], 0.f);

    const __nv_bfloat16* Qhs = (const __nv_bfloat16*)(smb + FQH);
    const __nv_bfloat16* Qls = (const __nv_bfloat16*)(smb + FQL);
    const __nv_bfloat16* Khs = (const __nv_bfloat16*)(smb + FKV);
    const __nv_bfloat16* Kls = (const __nv_bfloat16*)(smb + FKV + 9216);
    const __nv_bfloat16* Vhs = (const __nv_bfloat16*)(smb + FKV + 18432);
    const __nv_bfloat16* Vls = (const __nv_bfloat16*)(smb + FKV + 27648);

    const int ntiles = 2 * qt + 2;
    for (int kt = 0; kt < ntiles; kt++) {
        __pipeline_wait_prior(0);
        __syncthreads();                 // KV(kt) visible to all warps

        // ---- S = Q K^T : warp -> its 16 q-rows x 64 keys ----
        wmma::fragment<wmma::accumulator, 16, 16, 16, float> s[4];
        for (int ni = 0; ni < 4; ni++) wmma::fill_fragment(s[ni], 0.f);
        for (int ks = 0; ks < 4; ks++) {
            int kc = ks * 16;
            wmma::fragment<wmma::matrix_a, 16, 16, 16, __nv_bfloat16, wmma::row_major> qh, ql;
            wmma::load_matrix_sync(qh, Qhs + qr * 72 + kc, 72);
            wmma::load_matrix_sync(ql, Qls + qr * 72 + kc, 72);
            for (int ni = 0; ni < 4; ni++) {
                wmma::fragment<wmma::matrix_b, 16, 16, 16, __nv_bfloat16, wmma::col_major> kh, kl;
                wmma::load_matrix_sync(kh, Khs + (ni * 16) * 72 + kc, 72);
                wmma::load_matrix_sync(kl, Kls + (ni * 16) * 72 + kc, 72);
                wmma::mma_sync(s[ni], qh, kh, s[ni]);
                wmma::mma_sync(s[ni], qh, kl, s[ni]);
                wmma::mma_sync(s[ni], ql, kh, s[ni]);
            }
        }

        // ---- in-register mask + scale + warp-local row max ----
        const int cgA = q0 + rowA;
        const int cgB = q0 + rowB;
        const int colb = kt * 64 + c2;
        float mxA = -INFINITY, mxB = -INFINITY;
        for (int ni = 0; ni < 4; ni++) {
            int cb = colb + ni * 16;
            float t;
            t = s[ni].x[0] * 0.125f; if (cb     > cgA) t = -1e9f; s[ni].x[0] = t; mxA = fmaxf(mxA, t);
            t = s[ni].x[1] * 0.125f; if (cb + 1 > cgA) t = -1e9f; s[ni].x[1] = t; mxA = fmaxf(mxA, t);
            t = s[ni].x[4] * 0.125f; if (cb + 8 > cgA) t = -1e9f; s[ni].x[4] = t; mxA = fmaxf(mxA, t);
            t = s[ni].x[5] * 0.125f; if (cb + 9 > cgA) t = -1e9f; s[ni].x[5] = t; mxA = fmaxf(mxA, t);
            t = s[ni].x[2] * 0.125f; if (cb     > cgB) t = -1e9f; s[ni].x[2] = t; mxB = fmaxf(mxB, t);
            t = s[ni].x[3] * 0.125f; if (cb + 1 > cgB) t = -1e9f; s[ni].x[3] = t; mxB = fmaxf(mxB, t);
            t = s[ni].x[6] * 0.125f; if (cb + 8 > cgB) t = -1e9f; s[ni].x[6] = t; mxB = fmaxf(mxB, t);
            t = s[ni].x[7] * 0.125f; if (cb + 9 > cgB) t = -1e9f; s[ni].x[7] = t; mxB = fmaxf(mxB, t);
        }
        mxA = fmaxf(mxA, __shfl_xor_sync(0xffffffffu, mxA, 1));
        mxA = fmaxf(mxA, __shfl_xor_sync(0xffffffffu, mxA, 2));
        mxB = fmaxf(mxB, __shfl_xor_sync(0xffffffffu, mxB, 1));
        mxB = fmaxf(mxB, __shfl_xor_sync(0xffffffffu, mxB, 2));

        float mnewA = fmaxf(mA, mxA);
        float mnewB = fmaxf(mB, mxB);
        float scA = __expf(mA - mnewA);
        float scB = __expf(mB - mnewB);
        mA = mnewA;
        mB = mnewB;

        // ---- exp, P (hi/lo) to warp-private smem strip, row sums ----
        float sumA = 0.f, sumB = 0.f;
        __nv_bfloat16* PA = Pbuf + rowA * 144;
        __nv_bfloat16* PB = Pbuf + rowB * 144;
        for (int ni = 0; ni < 4; ni++) {
            float p0 = __expf(s[ni].x[0] - mnewA);
            float p1 = __expf(s[ni].x[1] - mnewA);
            float p4 = __expf(s[ni].x[4] - mnewA);
            float p5 = __expf(s[ni].x[5] - mnewA);
            float p2 = __expf(s[ni].x[2] - mnewB);
            float p3 = __expf(s[ni].x[3] - mnewB);
            float p6 = __expf(s[ni].x[6] - mnewB);
            float p7 = __expf(s[ni].x[7] - mnewB);
            sumA += (p0 + p1) + (p4 + p5);
            sumB += (p2 + p3) + (p6 + p7);
            int cl = ni * 16 + c2;
            store_p2(PA, cl,     p0, p1);
            store_p2(PA, cl + 8, p4, p5);
            store_p2(PB, cl,     p2, p3);
            store_p2(PB, cl + 8, p6, p7);
        }
        sumA += __shfl_xor_sync(0xffffffffu, sumA, 1);
        sumA += __shfl_xor_sync(0xffffffffu, sumA, 2);
        sumB += __shfl_xor_sync(0xffffffffu, sumB, 1);
        sumB += __shfl_xor_sync(0xffffffffu, sumB, 2);
        lA = lA * scA + sumA;
        lB = lB * scB + sumB;
        __syncwarp();                    // P strip visible within warp

        // ---- rescale O in registers, then O(16x64) += P(16x64) V(64x64) ----
        for (int ni = 0; ni < 4; ni++) scale_frag_rows(o[ni], scA, scB);
        for (int kc4 = 0; kc4 < 4; kc4++) {
            int kc = kc4 * 16;
            wmma::fragment<wmma::matrix_a, 16, 16, 16, __nv_bfloat16, wmma::row_major> ph, pl;
            wmma::load_matrix_sync(ph, Pbuf + qr * 144 + kc, 144);
            wmma::load_matrix_sync(pl, Pbuf + qr * 144 + 72 + kc, 144);
            for (int nd = 0; nd < 4; nd++) {
                wmma::fragment<wmma::matrix_b, 16, 16, 16, __nv_bfloat16, wmma::row_major> vh, vl;
                wmma::load_matrix_sync(vh, Vhs + kc * 72 + nd * 16, 72);
                wmma::load_matrix_sync(vl, Vls + kc * 72 + nd * 16, 72);
                wmma::mma_sync(o[nd], ph, vh, o[nd]);
                wmma::mma_sync(o[nd], ph, vl, o[nd]);
                wmma::mma_sync(o[nd], pl, vh, o[nd]);
            }
        }

        __syncthreads();                 // all warps done reading KV(kt)
        if (kt + 1 < ntiles) {
            char* kv = smb + FKV;
            int kb2 = b * S_ + (kt + 1) * 64;
            flash_load_64(kv,         Kh_g, kb2, h, tid);
            flash_load_64(kv + 9216,  Kl_g, kb2, h, tid);
            flash_load_64(kv + 18432, Vh_g, kb2, h, tid);
            flash_load_64(kv + 27648, Vl_g, kb2, h, tid);
            __pipeline_commit();
        }
    }

    // ---- epilogue: normalize in registers, stage to Obuf (aliases own P
    // rows; within-warp WAR safe), then cooperative global hi/lo write ----
    {
        float i0 = 1.f / lA;
        float i1 = 1.f / lB;
        for (int ni = 0; ni < 4; ni++) scale_frag_rows(o[ni], i0, i1);
        for (int ni = 0; ni < 4; ni++)
            wmma::store_matrix_sync(Obuf + qr * 72 + ni * 16, o[ni], 72,
                                    wmma::mem_row_major);
    }
    __syncthreads();
    for (int idx = tid; idx < 128 * 64; idx += 256) {
        int r = idx >> 6;
        int c = idx & 63;
        float v = Obuf[r * 72 + c];
        __nv_bfloat16 hv = __float2bfloat16(v);
        size_t g = (size_t)(b * S_ + q0 + r) * D_ + h * DK_ + c;
        Oh_g[g] = hv;
        Ol_g[g] = __float2bfloat16(v - __bfloat162float(hv));
    }
}

// ---------------------------------------------------------------------------
// Launch. Inputs: q,k,v,mask,Wq,bq,Wk,bk,Wv,bv,Wo,bo
// ---------------------------------------------------------------------------
extern "C" void kernel_launch(void* const* d_in, const int* in_sizes, int n_in,
                              void* d_out, int out_size)
{
    const float* q    = (const float*)d_in[0];
    const float* k    = (const float*)d_in[1];
    const float* v    = (const float*)d_in[2];
    const float* Wq   = (const float*)d_in[4];
    const float* bq   = (const float*)d_in[5];
    const float* Wk   = (const float*)d_in[6];
    const float* bk   = (const float*)d_in[7];
    const float* Wv   = (const float*)d_in[8];
    const float* bv   = (const float*)d_in[9];
    const float* Wo   = (const float*)d_in[10];
    const float* bo   = (const float*)d_in[11];
    float* out = (float*)d_out;

    __nv_bfloat16 *X1h, *X1l, *X2h, *X2l, *X3h, *X3l;
    __nv_bfloat16 *W1h, *W1l, *W2h, *W2l, *W3h, *W3l, *W4h, *W4l;
    __nv_bfloat16 *Qh, *Ql, *Kh, *Kl, *Vh, *Vl;
    cudaGetSymbolAddress((void**)&X1h, g_X1h);
    cudaGetSymbolAddress((void**)&X1l, g_X1l);
    cudaGetSymbolAddress((void**)&X2h, g_X2h);
    cudaGetSymbolAddress((void**)&X2l, g_X2l);
    cudaGetSymbolAddress((void**)&X3h, g_X3h);
    cudaGetSymbolAddress((void**)&X3l, g_X3l);
    cudaGetSymbolAddress((void**)&W1h, g_W1h);
    cudaGetSymbolAddress((void**)&W1l, g_W1l);
    cudaGetSymbolAddress((void**)&W2h, g_W2h);
    cudaGetSymbolAddress((void**)&W2l, g_W2l);
    cudaGetSymbolAddress((void**)&W3h, g_W3h);
    cudaGetSymbolAddress((void**)&W3l, g_W3l);
    cudaGetSymbolAddress((void**)&W4h, g_W4h);
    cudaGetSymbolAddress((void**)&W4l, g_W4l);
    cudaGetSymbolAddress((void**)&Qh, g_Qh);
    cudaGetSymbolAddress((void**)&Ql, g_Ql);
    cudaGetSymbolAddress((void**)&Kh, g_Kh);
    cudaGetSymbolAddress((void**)&Kl, g_Kl);
    cudaGetSymbolAddress((void**)&Vh, g_Vh);
    cudaGetSymbolAddress((void**)&Vl, g_Vl);

    cudaFuncSetAttribute(gemm_wmma_kernel,
                         cudaFuncAttributeMaxDynamicSharedMemorySize, SMEM_BYTES);
    cudaFuncSetAttribute(flash_wmma_kernel,
                         cudaFuncAttributeMaxDynamicSharedMemorySize, FLASH_SMEM);

    const int nX4 = M_ * D_ / 4;
    const int nW4 = D_ * D_ / 4;
    dim3 cvt8g((3 * nX4 + 4 * nW4 + 255) / 256);

    cvt8_kernel<<<cvt8g, 256>>>(
        (const float4*)q, X1h, X1l,
        (const float4*)k, X2h, X2l,
        (const float4*)v, X3h, X3l, nX4,
        (const float4*)Wq, W1h, W1l,
        (const float4*)Wk, W2h, W2l,
        (const float4*)Wv, W3h, W3l,
        (const float4*)Wo, W4h, W4l, nW4);

    GemmSet sq; sq.Xh = X1h; sq.Xl = X1l; sq.Wh = W1h; sq.Wl = W1l;
    sq.bias = bq; sq.Y = out; sq.Yh = Qh; sq.Yl = Ql; sq.split = 1;
    GemmSet sk; sk.Xh = X2h; sk.Xl = X2l; sk.Wh = W2h; sk.Wl = W2l;
    sk.bias = bk; sk.Y = out; sk.Yh = Kh; sk.Yl = Kl; sk.split = 1;
    GemmSet sv; sv.Xh = X3h; sv.Xl = X3l; sv.Wh = W3h; sv.Wl = W3l;
    sv.bias = bv; sv.Y = out; sv.Yh = Vh; sv.Yl = Vl; sv.split = 1;
    dim3 gqkv(D_ / BN, 3 * (M_ / BM));
    gemm_wmma_kernel<<<gqkv, 256, SMEM_BYTES>>>(sq, sk, sv, D_, D_);

    // Attention: 128 queries/CTA, warp-owns-rows.
    dim3 fgrid(S_ / 128, B_ * H_);   // (16, 32)
    flash_wmma_kernel<<<fgrid, 256, FLASH_SMEM>>>(Qh, Ql, Kh, Kl, Vh, Vl, X1h, X1l);

    GemmSet so; so.Xh = X1h; so.Xl = X1l; so.Wh = W4h; so.Wl = W4l;
    so.bias = bo; so.Y = out; so.Yh = Qh; so.Yl = Ql; so.split = 0;
    dim3 gout(D_ / BN, M_ / BM);
    gemm_wmma_kernel<<<gout, 256, SMEM_BYTES>>>(so, so, so, D_, D_);
}